// round 1
// baseline (speedup 1.0000x reference)
#include <cuda_runtime.h>
#include <math.h>

#define BB 256
#define VV 50257
#define UU 65536
#define MM 3
#define NE (MM * VV)   // 150771 total (model, vocab) entries

// ---------------- scratch (device globals; no allocation at launch time) ----
__device__ float g_probsT[(size_t)MM * VV * BB];   // [m][j][b], b contiguous (1KB rows)
__device__ float g_rmax[MM * BB];
__device__ float g_scale[MM * BB];                 // w_m / sum_exp
__device__ int   g_count[UU];
__device__ int   g_off[UU + 1];
__device__ int   g_cursor[UU];
__device__ int   g_entries[NE];                    // packed pidx = m*VV + j

// ---------------- CSR inverse-map build ------------------------------------
__global__ void zero_counts() {
    int i = blockIdx.x * blockDim.x + threadIdx.x;
    if (i < UU) g_count[i] = 0;
}

__global__ void count_entries(const int* __restrict__ m0,
                              const int* __restrict__ m1,
                              const int* __restrict__ m2) {
    int idx = blockIdx.x * blockDim.x + threadIdx.x;
    if (idx >= NE) return;
    int m = idx / VV;
    int j = idx - m * VV;
    const int* mp = (m == 0) ? m0 : (m == 1) ? m1 : m2;
    atomicAdd(&g_count[mp[j]], 1);
}

// exclusive scan of 65536 counts with one 1024-thread block (64 per thread)
__global__ void scan_counts() {
    __shared__ int s[1024];
    int t = threadIdx.x;
    int base = t * 64;
    int tot = 0;
#pragma unroll 8
    for (int i = 0; i < 64; i++) tot += g_count[base + i];
    s[t] = tot;
    __syncthreads();
    for (int o = 1; o < 1024; o <<= 1) {
        int v = (t >= o) ? s[t - o] : 0;
        __syncthreads();
        s[t] += v;
        __syncthreads();
    }
    int run = s[t] - tot;   // exclusive prefix for this thread's chunk
    for (int i = 0; i < 64; i++) {
        g_off[base + i]    = run;
        g_cursor[base + i] = run;
        run += g_count[base + i];
    }
    if (t == 1023) g_off[UU] = s[1023];
}

__global__ void fill_entries(const int* __restrict__ m0,
                             const int* __restrict__ m1,
                             const int* __restrict__ m2) {
    int idx = blockIdx.x * blockDim.x + threadIdx.x;
    if (idx >= NE) return;
    int m = idx / VV;
    int j = idx - m * VV;
    const int* mp = (m == 0) ? m0 : (m == 1) ? m1 : m2;
    int u = mp[j];
    int pos = atomicAdd(&g_cursor[u], 1);
    g_entries[pos] = idx;   // pidx = m*VV + j
}

// canonicalize entry order within each bucket (determinism across replays)
__global__ void sort_buckets() {
    int u = blockIdx.x * blockDim.x + threadIdx.x;
    if (u >= UU) return;
    int s = g_off[u], e = g_off[u + 1];
    for (int i = s + 1; i < e; i++) {
        int key = g_entries[i];
        int k = i - 1;
        while (k >= s && g_entries[k] > key) { g_entries[k + 1] = g_entries[k]; k--; }
        g_entries[k + 1] = key;
    }
}

// ---------------- softmax row stats (online max/sum) ------------------------
__global__ void rowstats(const float* __restrict__ l0,
                         const float* __restrict__ l1,
                         const float* __restrict__ l2,
                         const float* __restrict__ w) {
    int b = blockIdx.x, m = blockIdx.y, t = threadIdx.x;
    const float* row = ((m == 0) ? l0 : (m == 1) ? l1 : l2) + (size_t)b * VV;
    float mx = -1e30f, sm = 0.f;
    for (int j = t; j < VV; j += 256) {
        float x = row[j];
        if (x > mx) { sm = sm * __expf(mx - x) + 1.f; mx = x; }
        else        { sm += __expf(x - mx); }
    }
    __shared__ float smx[256], ssm[256];
    smx[t] = mx; ssm[t] = sm;
    __syncthreads();
    for (int s = 128; s > 0; s >>= 1) {
        if (t < s) {
            float amx = smx[t], as = ssm[t], bmx = smx[t + s], bs = ssm[t + s];
            float Mx = fmaxf(amx, bmx);
            ssm[t] = as * __expf(amx - Mx) + bs * __expf(bmx - Mx);
            smx[t] = Mx;
        }
        __syncthreads();
    }
    if (t == 0) {
        g_rmax[m * BB + b]  = smx[0];
        g_scale[m * BB + b] = w[m] / ssm[0];
    }
}

// ---------------- exp + transpose: logits[b][j] -> probsT[m][j][b] ----------
__global__ void exp_transpose(const float* __restrict__ l0,
                              const float* __restrict__ l1,
                              const float* __restrict__ l2) {
    __shared__ float tile[32][33];
    int m  = blockIdx.z;
    int j0 = blockIdx.x * 32;
    int b0 = blockIdx.y * 32;
    const float* lg = (m == 0) ? l0 : (m == 1) ? l1 : l2;
    int tx = threadIdx.x, ty = threadIdx.y;   // (32, 8)

#pragma unroll
    for (int k = 0; k < 4; k++) {
        int bl = ty + k * 8;
        int j  = j0 + tx;
        int b  = b0 + bl;
        float v = 0.f;
        if (j < VV) {
            float x  = lg[(size_t)b * VV + j];
            int rid  = m * BB + b;
            v = __expf(x - g_rmax[rid]) * g_scale[rid];
        }
        tile[bl][tx] = v;
    }
    __syncthreads();
#pragma unroll
    for (int k = 0; k < 4; k++) {
        int jl = ty + k * 8;
        int j  = j0 + jl;
        if (j < VV)
            g_probsT[((size_t)m * VV + j) * BB + b0 + tx] = tile[tx][jl];
    }
}

// ---------------- gather per union column, smem-transpose, coalesced write --
__global__ void gather_union(float* __restrict__ out) {
    __shared__ float tile[32][257];   // 32 u x 256 b, padded: conflict-free both ways
    int u0 = blockIdx.x * 32;
    int t  = threadIdx.x;             // 256 threads: thread t = batch index in phase 1

    for (int ul = 0; ul < 32; ul++) {
        int u = u0 + ul;
        int s = g_off[u], e = g_off[u + 1];
        float acc = 0.f;
        for (int ee = s; ee < e; ee++) {
            int p = g_entries[ee];
            acc += g_probsT[(size_t)p * BB + t];   // contiguous 1KB per entry
        }
        tile[ul][t] = acc;
    }
    __syncthreads();
    // write out[b][u0..u0+31]: 32-thread groups -> one 128B transaction each
    for (int it = 0; it < 32; it++) {
        int ul = t & 31;
        int b  = (t >> 5) + it * 8;
        out[(size_t)b * UU + u0 + ul] = tile[ul][b];
    }
}

// ---------------- launch -----------------------------------------------------
extern "C" void kernel_launch(void* const* d_in, const int* in_sizes, int n_in,
                              void* d_out, int out_size) {
    const float* l0 = (const float*)d_in[0];
    const float* l1 = (const float*)d_in[1];
    const float* l2 = (const float*)d_in[2];
    const int*   m0 = (const int*)d_in[3];
    const int*   m1 = (const int*)d_in[4];
    const int*   m2 = (const int*)d_in[5];
    const float* w  = (const float*)d_in[6];
    float* out = (float*)d_out;

    zero_counts<<<UU / 256, 256>>>();
    count_entries<<<(NE + 255) / 256, 256>>>(m0, m1, m2);
    scan_counts<<<1, 1024>>>();
    fill_entries<<<(NE + 255) / 256, 256>>>(m0, m1, m2);
    sort_buckets<<<UU / 256, 256>>>();

    rowstats<<<dim3(BB, MM), 256>>>(l0, l1, l2, w);
    exp_transpose<<<dim3((VV + 31) / 32, BB / 32, MM), dim3(32, 8)>>>(l0, l1, l2);
    gather_union<<<UU / 32, 256>>>(out);
}